// round 12
// baseline (speedup 1.0000x reference)
#include <cuda_runtime.h>
#include <cuda_fp16.h>
#include <math.h>
#include <stdint.h>

#define NH 4
#define HD 128
#define D  512
#define TS 24
#define NB 64
#define NPOS 32768
#define J   96
#define JP  104
#define BL  26624
#define TLB 6656
#define SCALE 0.08838834764831845f

__device__ __align__(16)  float g_Bq[TS*NH*HD];
__device__ __align__(16)  float g_K [TS*NH*HD];
__device__ __align__(16)  float g_V [TS*NH*HD];
__device__ __align__(16)  float g_G [J*D];
__device__ __align__(16)  float g_T [TS*NH*TS];
__device__ __align__(128) __half g_Bh[D*JP];
__device__ __align__(128) __half g_Bl[D*JP];
__device__ __align__(128) __half g_Th[32*JP];
__device__ __align__(128) __half g_Tl[32*JP];

__device__ __forceinline__ uint32_t smem_u32(const void* p){
    uint32_t a;
    asm("{ .reg .u64 t; cvta.to.shared.u64 t, %1; cvt.u32.u64 %0, t; }" : "=r"(a) : "l"(p));
    return a;
}
__device__ __forceinline__ void bulk_g2s(uint32_t dst, const void* src,
                                         uint32_t bytes, uint32_t mbar){
    asm volatile(
        "cp.async.bulk.shared::cluster.global.mbarrier::complete_tx::bytes [%0], [%1], %2, [%3];"
        :: "r"(dst), "l"(src), "r"(bytes), "r"(mbar) : "memory");
}
#define MBAR_INIT(a, c)  asm volatile("mbarrier.init.shared.b64 [%0], %1;" :: "r"(a), "r"(c) : "memory")
#define MBAR_EXPECT(a,b) asm volatile("mbarrier.arrive.expect_tx.shared.b64 _, [%0], %1;" :: "r"(a), "r"(b) : "memory")
#define MBAR_WAIT(a, ph) do { \
    uint32_t _m=(a), _p=(ph), _d; \
    asm volatile("{\n\t.reg .pred p;\n\t" \
        "mbarrier.try_wait.parity.acquire.cta.shared::cta.b64 p, [%1], %2;\n\t" \
        "selp.b32 %0, 1, 0, p;\n\t}" : "=r"(_d) : "r"(_m), "r"(_p) : "memory"); \
    if (!_d) { asm volatile("{\n\t.reg .pred P1;\n\t" \
        "W_%=:\n\tmbarrier.try_wait.parity.acquire.cta.shared::cta.b64 P1, [%0], %1, 0x989680;\n\t" \
        "@P1 bra.uni WD_%=;\n\tbra.uni W_%=;\n\tWD_%=:\n\t}" :: "r"(_m), "r"(_p) : "memory"); } \
} while(0)

#define MMA16816(c, a, b0v, b1v) \
    asm volatile("mma.sync.aligned.m16n8k16.row.col.f32.f16.f16.f32 " \
        "{%0,%1,%2,%3}, {%4,%5,%6,%7}, {%8,%9}, {%0,%1,%2,%3};" \
        : "+f"((c)[0]), "+f"((c)[1]), "+f"((c)[2]), "+f"((c)[3]) \
        : "r"((a)[0]), "r"((a)[1]), "r"((a)[2]), "r"((a)[3]), \
          "r"(b0v), "r"(b1v))

#define LDMX4(r, addr) \
    asm volatile("ldmatrix.sync.aligned.m8n8.x4.shared.b16 {%0,%1,%2,%3}, [%4];" \
        : "=r"((r)[0]), "=r"((r)[1]), "=r"((r)[2]), "=r"((r)[3]) : "r"(addr))

__device__ __forceinline__ float wredsum(float v){
    #pragma unroll
    for (int o = 16; o; o >>= 1) v += __shfl_xor_sync(0xFFFFFFFFu, v, o);
    return v;
}
__device__ __forceinline__ float dot4(float4 a, float4 b){
    return fmaf(a.x,b.x, fmaf(a.y,b.y, fmaf(a.z,b.z, a.w*b.w)));
}

// ---------------- K_p1: Bq, K, V ----------------
__global__ void __launch_bounds__(256)
k_p1(const float* __restrict__ ts_emb,
     const float* __restrict__ Wq, const float* __restrict__ bq,
     const float* __restrict__ Wk, const float* __restrict__ bk,
     const float* __restrict__ Wv, const float* __restrict__ bv)
{
    const int wid  = threadIdx.x >> 5;
    const int lane = threadIdx.x & 31;
    const int rg   = blockIdx.x >> 6;
    const int he   = (blockIdx.x & 63)*8 + wid;

    const float* w;
    float bias;
    float* dst;
    int g;
    if (rg < 3) {
        g = rg;  w = Wq + (size_t)he*1024 + 512; bias = __ldg(bq + he); dst = g_Bq;
    } else if (rg < 6) {
        g = rg - 3; w = Wk + (size_t)he*512; bias = __ldg(bk + he); dst = g_K;
    } else {
        g = rg - 6; w = Wv + (size_t)he*512; bias = __ldg(bv + he); dst = g_V;
    }
    const float* x[8];
    #pragma unroll
    for (int i = 0; i < 8; i++) x[i] = ts_emb + (g*8 + i)*D;

    float acc[8] = {0,0,0,0,0,0,0,0};
    #pragma unroll
    for (int ch = 0; ch < 4; ch++) {
        int e = ch*128 + lane*4;
        float4 w4 = __ldg((const float4*)(w + e));
        #pragma unroll
        for (int i = 0; i < 8; i++) {
            float4 x4 = __ldg((const float4*)(x[i] + e));
            acc[i] = fmaf(w4.x,x4.x, fmaf(w4.y,x4.y, fmaf(w4.z,x4.z, fmaf(w4.w,x4.w, acc[i]))));
        }
    }
    float r = 0.f;
    #pragma unroll
    for (int i = 0; i < 8; i++) {
        float s = wredsum(acc[i]);
        if (lane == i) r = s;
    }
    if (lane < 8)
        dst[(size_t)(g*8 + lane)*D + he] = r + bias;
}

// ---------------- K_p2: G fold + VU/TL folds + T table ----------------
__global__ void __launch_bounds__(256)
k_p2(const float* __restrict__ Wq,
     const float* __restrict__ Wu, const float* __restrict__ Wt)
{
    const int wid  = threadIdx.x >> 5;
    const int lane = threadIdx.x & 31;

    if (blockIdx.x < 768) {
        const int bi  = blockIdx.x;
        const int h   = bi / 192;
        const int rem = bi - h*192;
        const int dg  = rem / 3;
        const int kg  = rem - dg*3;
        const int k   = kg*8 + wid;

        const float* kptr = g_K + (k*NH + h)*HD;
        float acc[8] = {0,0,0,0,0,0,0,0};
        #pragma unroll
        for (int ec = 0; ec < 4; ec++) {
            const int e = ec*32 + lane;
            const float kv = kptr[e];
            const float* wp = Wq + ((size_t)(h*HD + e))*1024 + dg*8;
            float4 w0 = __ldg((const float4*)wp);
            float4 w1 = __ldg((const float4*)(wp + 4));
            acc[0] = fmaf(w0.x, kv, acc[0]);
            acc[1] = fmaf(w0.y, kv, acc[1]);
            acc[2] = fmaf(w0.z, kv, acc[2]);
            acc[3] = fmaf(w0.w, kv, acc[3]);
            acc[4] = fmaf(w1.x, kv, acc[4]);
            acc[5] = fmaf(w1.y, kv, acc[5]);
            acc[6] = fmaf(w1.z, kv, acc[6]);
            acc[7] = fmaf(w1.w, kv, acc[7]);
        }
        float r = 0.f;
        #pragma unroll
        for (int i = 0; i < 8; i++) {
            float s = wredsum(acc[i]);
            if (lane == i) r = s;
        }
        if (lane < 8)
            g_G[(size_t)(h*TS + k)*D + dg*8 + lane] = r * SCALE;
        return;
    }

    int task = (blockIdx.x - 768)*8 + wid;
    if (task < 6144) {
        int j  = task >> 6;
        int dg = task & 63;
        int h = j / TS, k = j - h*TS;
        float4 vr = *(const float4*)(g_V + (k*NH + h)*HD + lane*4);
        const float* wbase = Wu + h*HD + lane*4;
        float val = 0.f;
        #pragma unroll
        for (int dd = 0; dd < 8; dd++) {
            int d = dg*8 + dd;
            float4 w4 = __ldg((const float4*)(wbase + (size_t)d*D));
            float s = wredsum(dot4(vr, w4));
            if (lane == dd) val = s;
        }
        if (lane < 8) {
            int d = dg*8 + lane;
            __half hi = __float2half_rn(val);
            __half lo = __float2half_rn(val - __half2float(hi));
            g_Bh[(size_t)d*JP + j] = hi;
            g_Bl[(size_t)d*JP + j] = lo;
        }
    } else if (task < 6432) {
        int t2 = task - 6144;
        int j  = t2 / 3;
        int dg = t2 - j*3;
        int h = j / TS, k = j - h*TS;
        float4 vr = *(const float4*)(g_V + (k*NH + h)*HD + lane*4);
        const float* wbase = Wt + h*HD + lane*4;
        float val = 0.f;
        #pragma unroll
        for (int dd = 0; dd < 8; dd++) {
            int d = dg*8 + dd;
            float4 w4 = __ldg((const float4*)(wbase + (size_t)d*D));
            float s = wredsum(dot4(vr, w4));
            if (lane == dd) val = s;
        }
        if (lane < 8) {
            int d = dg*8 + lane;
            __half hi = __float2half_rn(val);
            __half lo = __float2half_rn(val - __half2float(hi));
            g_Th[(size_t)d*JP + j] = hi;
            g_Tl[(size_t)d*JP + j] = lo;
        }
    } else if (task < 6720) {
        int t2 = task - 6432;
        int j  = t2 / 3;
        int tg = t2 - j*3;
        int h = j / TS, k = j - h*TS;
        float4 kv = *(const float4*)(g_K + (k*NH + h)*HD + lane*4);
        float val = 0.f;
        #pragma unroll
        for (int i = 0; i < 8; i++) {
            float4 b4 = *(const float4*)(g_Bq + ((tg*8 + i)*NH + h)*HD + lane*4);
            float s = wredsum(dot4(kv, b4));
            if (lane == i) val = s;
        }
        if (lane < 8)
            g_T[((tg*8 + lane)*NH + h)*TS + k] = val * SCALE;
    }
}

// ---------------- k_main ----------------
#define FM_U     16
#define FM_A     512
#define FM_B     27136
#define FM_TOTAL 80384

__global__ void __launch_bounds__(256, 2)
k_main(const int* __restrict__ user_x, const float* __restrict__ upt,
       const int* __restrict__ hour_x, const int* __restrict__ hour_mask,
       const float* __restrict__ b_unify, const float* __restrict__ b_time,
       float* __restrict__ out_emb, float* __restrict__ out_tl)
{
    extern __shared__ char sm[];
    const uint32_t sb = smem_u32(sm);
    const int tid  = threadIdx.x;
    const int wid  = tid >> 5;
    const int lane = tid & 31;
    const int n0   = blockIdx.x * 128;

    if (tid == 0) {
        MBAR_INIT(sb + 0, 1);
        MBAR_EXPECT(sb + 0, 2*BL);
        bulk_g2s(sb + FM_B,      g_Bh, BL, sb + 0);
        bulk_g2s(sb + FM_B + BL, g_Bl, BL, sb + 0);
    }

    float* sU = (float*)(sm + FM_U);
    if (tid < 96) {
        const float* up = upt + (size_t)__ldg(user_x + (n0 >> 9))*D;
        const float* gr = g_G + (size_t)tid*D;
        float a0 = 0.f, a1 = 0.f;
        #pragma unroll 4
        for (int d = 0; d < D; d += 8) {
            float4 u0 = __ldg((const float4*)(up + d));
            float4 q0 = __ldg((const float4*)(gr + d));
            float4 u1 = __ldg((const float4*)(up + d + 4));
            float4 q1 = __ldg((const float4*)(gr + d + 4));
            a0 = fmaf(u0.x,q0.x, fmaf(u0.y,q0.y, fmaf(u0.z,q0.z, fmaf(u0.w,q0.w, a0))));
            a1 = fmaf(u1.x,q1.x, fmaf(u1.y,q1.y, fmaf(u1.z,q1.z, fmaf(u1.w,q1.w, a1))));
        }
        sU[tid] = a0 + a1;
    }
    __syncthreads();

    #pragma unroll
    for (int r = 0; r < 2; r++) {
        const int task = r*256 + tid;
        const int p = task & 127;
        const int h = task >> 7;
        const int n = n0 + p;
        const int t = __ldg(hour_x + n);
        const float* trow = g_T + (t*NH + h)*TS;
        const float* urow = sU + h*TS;
        const int4*  mrow = (const int4*)(hour_mask + (size_t)n*TS);
        float wv[TS]; float sum = 0.f;
        #pragma unroll
        for (int q = 0; q < 6; q++) {
            int4   m = __ldg(mrow + q);
            float4 tv = *(const float4*)(trow + q*4);
            float e0 = expf(urow[q*4+0] + tv.x);
            float e1 = expf(urow[q*4+1] + tv.y);
            float e2 = expf(urow[q*4+2] + tv.z);
            float e3 = expf(urow[q*4+3] + tv.w);
            wv[4*q+0] = (m.x == 1) ? 0.f : e0;
            wv[4*q+1] = (m.y == 1) ? 0.f : e1;
            wv[4*q+2] = (m.z == 1) ? 0.f : e2;
            wv[4*q+3] = (m.w == 1) ? 0.f : e3;
            sum += (wv[4*q+0]+wv[4*q+1]) + (wv[4*q+2]+wv[4*q+3]);
        }
        const float inv = 1.f / sum;
        uint32_t w12[12];
        #pragma unroll
        for (int q = 0; q < 12; q++) {
            __half h0 = __float2half_rn(wv[2*q]*inv);
            __half h1 = __float2half_rn(wv[2*q+1]*inv);
            w12[q] = (uint32_t)__half_as_ushort(h1) << 16 | __half_as_ushort(h0);
        }
        uint4* dhp = (uint4*)(sm + FM_A + p*208 + h*48);
        dhp[0] = make_uint4(w12[0],w12[1],w12[2],w12[3]);
        dhp[1] = make_uint4(w12[4],w12[5],w12[6],w12[7]);
        dhp[2] = make_uint4(w12[8],w12[9],w12[10],w12[11]);
    }
    __syncthreads();

    const int wm = wid & 3, wn = wid >> 2;
    const int grp = lane >> 2, qid = lane & 3;
    const int am = lane >> 3, r8 = lane & 7;

    const uint32_t aBase = sb + FM_A
        + (uint32_t)(wm*32 + (am & 1)*8 + r8)*208u + (uint32_t)((am >> 1) & 1)*16u;
    const uint32_t bLane = (uint32_t)(((am >> 1) & 1)*8 + r8)*208u + (uint32_t)(am & 1)*16u;

    for (int c = 0; c < 4; c++) {
        MBAR_WAIT(sb + 0, c & 1);

        float acc[2][2][4][4];
        #pragma unroll
        for (int mt = 0; mt < 2; mt++)
            #pragma unroll
            for (int nh = 0; nh < 2; nh++)
                #pragma unroll
                for (int nt = 0; nt < 4; nt++)
                    #pragma unroll
                    for (int k = 0; k < 4; k++) acc[mt][nh][nt][k] = 0.f;

        #pragma unroll
        for (int ks = 0; ks < 6; ks++) {
            uint32_t ah[2][4];
            LDMX4(ah[0], aBase + ks*32);
            LDMX4(ah[1], aBase + ks*32 + 16*208);
            #pragma unroll
            for (int nh = 0; nh < 2; nh++) {
                const uint32_t bk = sb + FM_B + (uint32_t)(wn*64 + nh*32)*208u + bLane + ks*32;
                uint32_t bh[2][4], bl[2][4];
                LDMX4(bh[0], bk);
                LDMX4(bh[1], bk + 16*208);
                LDMX4(bl[0], bk + BL);
                LDMX4(bl[1], bk + BL + 16*208);
                #pragma unroll
                for (int mt = 0; mt < 2; mt++)
                    #pragma unroll
                    for (int nt = 0; nt < 4; nt++) {
                        const int pr = nt >> 1, sub = (nt & 1)*2;
                        MMA16816(acc[mt][nh][nt], ah[mt], bh[pr][sub], bh[pr][sub+1]);
                        MMA16816(acc[mt][nh][nt], ah[mt], bl[pr][sub], bl[pr][sub+1]);
                    }
            }
        }

        #pragma unroll
        for (int nh = 0; nh < 2; nh++)
            #pragma unroll
            for (int nt = 0; nt < 4; nt++) {
                int d = c*128 + wn*64 + nh*32 + nt*8 + qid*2;
                float bx = __ldg(b_unify + d), by = __ldg(b_unify + d + 1);
                #pragma unroll
                for (int mt = 0; mt < 2; mt++) {
                    int row = n0 + wm*32 + mt*16 + grp;
                    float2 o0 = make_float2(acc[mt][nh][nt][0] + bx, acc[mt][nh][nt][1] + by);
                    float2 o1 = make_float2(acc[mt][nh][nt][2] + bx, acc[mt][nh][nt][3] + by);
                    *(float2*)(out_emb + (size_t)row*D + d)     = o0;
                    *(float2*)(out_emb + (size_t)(row+8)*D + d) = o1;
                }
            }
        __syncthreads();
        if (tid == 0) {
            if (c < 3) {
                MBAR_EXPECT(sb + 0, 2*BL);
                bulk_g2s(sb + FM_B,      g_Bh + (size_t)(c+1)*128*JP, BL, sb + 0);
                bulk_g2s(sb + FM_B + BL, g_Bl + (size_t)(c+1)*128*JP, BL, sb + 0);
            } else {
                MBAR_EXPECT(sb + 0, 2*TLB);
                bulk_g2s(sb + FM_B,      g_Th, TLB, sb + 0);
                bulk_g2s(sb + FM_B + BL, g_Tl, TLB, sb + 0);
            }
        }
    }

    MBAR_WAIT(sb + 0, 0);
    if (wn == 0) {
        float acc[2][4][4];
        #pragma unroll
        for (int mt = 0; mt < 2; mt++)
            #pragma unroll
            for (int nt = 0; nt < 4; nt++)
                #pragma unroll
                for (int k = 0; k < 4; k++) acc[mt][nt][k] = 0.f;

        #pragma unroll
        for (int ks = 0; ks < 6; ks++) {
            uint32_t ah[2][4];
            LDMX4(ah[0], aBase + ks*32);
            LDMX4(ah[1], aBase + ks*32 + 16*208);
            const uint32_t bk = sb + FM_B + bLane + ks*32;
            uint32_t bh[2][4], bl[2][4];
            LDMX4(bh[0], bk);
            LDMX4(bh[1], bk + 16*208);
            LDMX4(bl[0], bk + BL);
            LDMX4(bl[1], bk + BL + 16*208);
            #pragma unroll
            for (int mt = 0; mt < 2; mt++)
                #pragma unroll
                for (int nt = 0; nt < 4; nt++) {
                    const int pr = nt >> 1, sub = (nt & 1)*2;
                    MMA16816(acc[mt][nt], ah[mt], bh[pr][sub], bh[pr][sub+1]);
                    MMA16816(acc[mt][nt], ah[mt], bl[pr][sub], bl[pr][sub+1]);
                }
        }
        #pragma unroll
        for (int nt = 0; nt < 3; nt++) {
            int d = nt*8 + qid*2;
            float bx = __ldg(b_time + d), by = __ldg(b_time + d + 1);
            #pragma unroll
            for (int mt = 0; mt < 2; mt++) {
                int row = n0 + wm*32 + mt*16 + grp;
                float2 o0 = make_float2(acc[mt][nt][0] + bx, acc[mt][nt][1] + by);
                float2 o1 = make_float2(acc[mt][nt][2] + bx, acc[mt][nt][3] + by);
                *(float2*)(out_tl + (size_t)row*TS + d)     = o0;
                *(float2*)(out_tl + (size_t)(row+8)*TS + d) = o1;
            }
        }
    }
}

// ---------------- launch ----------------
extern "C" void kernel_launch(void* const* d_in, const int* in_sizes, int n_in,
                              void* d_out, int out_size)
{
    const float* ts_emb    = (const float*)d_in[0];
    const int*   user_x    = (const int*)  d_in[3];
    const int*   hour_x    = (const int*)  d_in[4];
    const int*   hour_mask = (const int*)  d_in[5];
    const float* upt       = (const float*)d_in[6];
    const float* Wq        = (const float*)d_in[7];
    const float* bq        = (const float*)d_in[8];
    const float* Wk        = (const float*)d_in[9];
    const float* bk        = (const float*)d_in[10];
    const float* Wv        = (const float*)d_in[11];
    const float* bv        = (const float*)d_in[12];
    const float* Wu        = (const float*)d_in[13];
    const float* bu        = (const float*)d_in[14];
    const float* Wt        = (const float*)d_in[15];
    const float* bt        = (const float*)d_in[16];

    float* out_emb = (float*)d_out;
    float* out_tl  = out_emb + (size_t)NPOS * D;

    cudaFuncSetAttribute(k_main, cudaFuncAttributeMaxDynamicSharedMemorySize, FM_TOTAL);

    k_p1<<<576, 256>>>(ts_emb, Wq, bq, Wk, bk, Wv, bv);
    k_p2<<<1608, 256>>>(Wq, Wu, Wt);
    k_main<<<256, 256, FM_TOTAL>>>(user_x, upt, hour_x, hour_mask, bu, bt, out_emb, out_tl);
}

// round 13
// speedup vs baseline: 2.1237x; 2.1237x over previous
#include <cuda_runtime.h>
#include <cuda_fp16.h>
#include <math.h>
#include <stdint.h>

#define NH 4
#define HD 128
#define D  512
#define TS 24
#define NB 64
#define NPOS 32768
#define J   96
#define JP  104
#define BL  26624     /* bytes per big B half-tile (128 rows x 208B) */
#define TLB 6656      /* bytes per TL half-tile (32 rows x 208B) */
#define SCALE 0.08838834764831845f

// ---------------- device scratch ----------------
__device__ __align__(16)  float g_A [NB*NH*HD];   // rows b: [b][he]
__device__ __align__(16)  float g_Bq[TS*NH*HD];   // rows t
__device__ __align__(16)  float g_K [TS*NH*HD];   // rows k
__device__ __align__(16)  float g_V [TS*NH*HD];   // rows k
__device__ __align__(16)  float g_U [NB*NH*TS];   // U[b][h][k] = scale*A_b.K_k
__device__ __align__(16)  float g_T [TS*NH*TS];   // T[t][h][k] = scale*Bq_t.K_k
__device__ __align__(128) __half g_Bh[D*JP];      // VU^T hi fp16: [d][j], 208B rows
__device__ __align__(128) __half g_Bl[D*JP];      // VU^T lo fp16
__device__ __align__(128) __half g_Th[32*JP];     // TL hi (rows 24..31 zero)
__device__ __align__(128) __half g_Tl[32*JP];     // TL lo

// ---------------- helpers ----------------
__device__ __forceinline__ uint32_t smem_u32(const void* p){
    uint32_t a;
    asm("{ .reg .u64 t; cvta.to.shared.u64 t, %1; cvt.u32.u64 %0, t; }" : "=r"(a) : "l"(p));
    return a;
}
__device__ __forceinline__ void bulk_g2s(uint32_t dst, const void* src,
                                         uint32_t bytes, uint32_t mbar){
    asm volatile(
        "cp.async.bulk.shared::cluster.global.mbarrier::complete_tx::bytes [%0], [%1], %2, [%3];"
        :: "r"(dst), "l"(src), "r"(bytes), "r"(mbar) : "memory");
}
#define MBAR_INIT(a, c)  asm volatile("mbarrier.init.shared.b64 [%0], %1;" :: "r"(a), "r"(c) : "memory")
#define MBAR_EXPECT(a,b) asm volatile("mbarrier.arrive.expect_tx.shared.b64 _, [%0], %1;" :: "r"(a), "r"(b) : "memory")
#define MBAR_WAIT(a, ph) do { \
    uint32_t _m=(a), _p=(ph), _d; \
    asm volatile("{\n\t.reg .pred p;\n\t" \
        "mbarrier.try_wait.parity.acquire.cta.shared::cta.b64 p, [%1], %2;\n\t" \
        "selp.b32 %0, 1, 0, p;\n\t}" : "=r"(_d) : "r"(_m), "r"(_p) : "memory"); \
    if (!_d) { asm volatile("{\n\t.reg .pred P1;\n\t" \
        "W_%=:\n\tmbarrier.try_wait.parity.acquire.cta.shared::cta.b64 P1, [%0], %1, 0x989680;\n\t" \
        "@P1 bra.uni WD_%=;\n\tbra.uni W_%=;\n\tWD_%=:\n\t}" :: "r"(_m), "r"(_p) : "memory"); } \
} while(0)

#define MMA16816(c, a, b0v, b1v) \
    asm volatile("mma.sync.aligned.m16n8k16.row.col.f32.f16.f16.f32 " \
        "{%0,%1,%2,%3}, {%4,%5,%6,%7}, {%8,%9}, {%0,%1,%2,%3};" \
        : "+f"((c)[0]), "+f"((c)[1]), "+f"((c)[2]), "+f"((c)[3]) \
        : "r"((a)[0]), "r"((a)[1]), "r"((a)[2]), "r"((a)[3]), \
          "r"(b0v), "r"(b1v))

#define LDMX4(r, addr) \
    asm volatile("ldmatrix.sync.aligned.m8n8.x4.shared.b16 {%0,%1,%2,%3}, [%4];" \
        : "=r"((r)[0]), "=r"((r)[1]), "=r"((r)[2]), "=r"((r)[3]) : "r"(addr))

__device__ __forceinline__ float wredsum(float v){
    #pragma unroll
    for (int o = 16; o; o >>= 1) v += __shfl_xor_sync(0xFFFFFFFFu, v, o);
    return v;
}
__device__ __forceinline__ float dot4(float4 a, float4 b){
    return fmaf(a.x,b.x, fmaf(a.y,b.y, fmaf(a.z,b.z, a.w*b.w)));
}

// ---------------- K1: A, Bq, K, V (identical to R10) ----------------
__global__ void __launch_bounds__(256)
k_pre1(const float* __restrict__ ts_emb, const int* __restrict__ user_x,
       const float* __restrict__ upt,
       const float* __restrict__ Wq, const float* __restrict__ bq,
       const float* __restrict__ Wk, const float* __restrict__ bk,
       const float* __restrict__ Wv, const float* __restrict__ bv)
{
    const int wid  = threadIdx.x >> 5;
    const int lane = threadIdx.x & 31;
    const int rg   = blockIdx.x >> 6;
    const int he   = (blockIdx.x & 63)*8 + wid;

    const float* w;
    const float* x[8];
    float bias = 0.f;
    float* dst;
    int row0;
    if (rg < 8) {
        w = Wq + (size_t)he*1024; dst = g_A; row0 = rg*8;
        #pragma unroll
        for (int i = 0; i < 8; i++)
            x[i] = upt + (size_t)__ldg(user_x + rg*8 + i)*D;
    } else if (rg < 11) {
        int g = rg - 8;
        w = Wq + (size_t)he*1024 + 512; bias = __ldg(bq + he);
        dst = g_Bq; row0 = g*8;
        #pragma unroll
        for (int i = 0; i < 8; i++) x[i] = ts_emb + (g*8 + i)*D;
    } else if (rg < 14) {
        int g = rg - 11;
        w = Wk + (size_t)he*512; bias = __ldg(bk + he);
        dst = g_K; row0 = g*8;
        #pragma unroll
        for (int i = 0; i < 8; i++) x[i] = ts_emb + (g*8 + i)*D;
    } else {
        int g = rg - 14;
        w = Wv + (size_t)he*512; bias = __ldg(bv + he);
        dst = g_V; row0 = g*8;
        #pragma unroll
        for (int i = 0; i < 8; i++) x[i] = ts_emb + (g*8 + i)*D;
    }

    float acc[8] = {0,0,0,0,0,0,0,0};
    #pragma unroll
    for (int ch = 0; ch < 4; ch++) {
        int e = ch*128 + lane*4;
        float4 w4 = __ldg((const float4*)(w + e));
        #pragma unroll
        for (int i = 0; i < 8; i++) {
            float4 x4 = __ldg((const float4*)(x[i] + e));
            acc[i] = fmaf(w4.x,x4.x, fmaf(w4.y,x4.y, fmaf(w4.z,x4.z, fmaf(w4.w,x4.w, acc[i]))));
        }
    }
    float r = 0.f;
    #pragma unroll
    for (int i = 0; i < 8; i++) {
        float s = wredsum(acc[i]);
        if (lane == i) r = s;
    }
    if (lane < 8)
        dst[(size_t)(row0 + lane)*D + he] = r + bias;
}

// ---------------- K23: VU/TL folds (fp16 hi/lo) + U/T score tables ----------------
__global__ void __launch_bounds__(256)
k_pre23(const float* __restrict__ Wu, const float* __restrict__ Wt)
{
    const int wid  = threadIdx.x >> 5;
    const int lane = threadIdx.x & 31;
    if (blockIdx.x < 804) {
        int task = blockIdx.x*8 + wid;
        if (task < 6144) {
            int j  = task >> 6;
            int dg = task & 63;
            int h = j / TS, k = j - h*TS;
            float4 vr = *(const float4*)(g_V + (size_t)k*D + h*HD + lane*4);
            const float* wbase = Wu + h*HD + lane*4;
            float val = 0.f;
            #pragma unroll
            for (int dd = 0; dd < 8; dd++) {
                int d = dg*8 + dd;
                float4 w4 = __ldg((const float4*)(wbase + (size_t)d*D));
                float s = wredsum(dot4(vr, w4));
                if (lane == dd) val = s;
            }
            if (lane < 8) {
                int d = dg*8 + lane;
                __half hi = __float2half_rn(val);
                __half lo = __float2half_rn(val - __half2float(hi));
                g_Bh[(size_t)d*JP + j] = hi;
                g_Bl[(size_t)d*JP + j] = lo;
            }
        } else if (task < 6432) {
            int t2 = task - 6144;
            int j  = t2 / 3;
            int dg = t2 - j*3;
            int h = j / TS, k = j - h*TS;
            float4 vr = *(const float4*)(g_V + (size_t)k*D + h*HD + lane*4);
            const float* wbase = Wt + h*HD + lane*4;
            float val = 0.f;
            #pragma unroll
            for (int dd = 0; dd < 8; dd++) {
                int d = dg*8 + dd;
                float4 w4 = __ldg((const float4*)(wbase + (size_t)d*D));
                float s = wredsum(dot4(vr, w4));
                if (lane == dd) val = s;
            }
            if (lane < 8) {
                int d = dg*8 + lane;
                __half hi = __float2half_rn(val);
                __half lo = __float2half_rn(val - __half2float(hi));
                g_Th[(size_t)d*JP + j] = hi;
                g_Tl[(size_t)d*JP + j] = lo;
            }
        }
    } else {
        // U/T score tables: 132 blocks, 1056 warp-tasks
        int task = (blockIdx.x - 804)*8 + wid;
        if (task < 768) {
            // U[b][h][kg*8..+8] = scale * A_b . K_k  (128-dot)
            int b   = task / 12;
            int rem = task - b*12;
            int h   = rem / 3;
            int kg  = rem - h*3;
            float4 av = *(const float4*)(g_A + (size_t)b*D + h*HD + lane*4);
            float val = 0.f;
            #pragma unroll
            for (int dd = 0; dd < 8; dd++) {
                int k = kg*8 + dd;
                float4 kv = *(const float4*)(g_K + (size_t)k*D + h*HD + lane*4);
                float s = wredsum(dot4(av, kv));
                if (lane == dd) val = s;
            }
            if (lane < 8)
                g_U[(b*NH + h)*TS + kg*8 + lane] = val * SCALE;
        } else if (task < 1056) {
            // T[t][h][kg*8..+8] = scale * Bq_t . K_k
            int t2  = task - 768;
            int t   = t2 / 12;
            int rem = t2 - t*12;
            int h   = rem / 3;
            int kg  = rem - h*3;
            float4 bv = *(const float4*)(g_Bq + (size_t)t*D + h*HD + lane*4);
            float val = 0.f;
            #pragma unroll
            for (int dd = 0; dd < 8; dd++) {
                int k = kg*8 + dd;
                float4 kv = *(const float4*)(g_K + (size_t)k*D + h*HD + lane*4);
                float s = wredsum(dot4(bv, kv));
                if (lane == dd) val = s;
            }
            if (lane < 8)
                g_T[(t*NH + h)*TS + kg*8 + lane] = val * SCALE;
        }
    }
}

// ---------------- k_main: inline-exp softmax + A fp16 + 2-pass HMMA, TL via MMA ----------------
#define FM_MBAR  0
#define FM_A     128
#define FM_B     26752            /* B buffer: hi @0, lo @+BL */
#define FM_TOTAL 80000

__global__ void __launch_bounds__(256, 2)
k_main(const int* __restrict__ hour_x, const int* __restrict__ hour_mask,
       const float* __restrict__ b_unify, const float* __restrict__ b_time,
       float* __restrict__ out_emb, float* __restrict__ out_tl)
{
    extern __shared__ char sm[];
    const uint32_t sb = smem_u32(sm);
    const int tid  = threadIdx.x;
    const int wid  = tid >> 5;
    const int lane = tid & 31;
    const int n0   = blockIdx.x * 128;

    // chunk 0 load starts immediately
    if (tid == 0) {
        MBAR_INIT(sb + FM_MBAR, 1);
        MBAR_EXPECT(sb + FM_MBAR, 2*BL);
        bulk_g2s(sb + FM_B,      g_Bh, BL, sb + FM_MBAR);
        bulk_g2s(sb + FM_B + BL, g_Bl, BL, sb + FM_MBAR);
    }

    // ---- softmax from U+T (inline exp) -> A fp16 tile: tasks (p,h), 2/thread ----
    const int bb = n0 >> 9;
    #pragma unroll
    for (int r = 0; r < 2; r++) {
        const int task = r*256 + tid;
        const int p = task & 127;
        const int h = task >> 7;
        const int n = n0 + p;
        const int t = __ldg(hour_x + n);
        const float* urow = g_U + (bb*NH + h)*TS;
        const float* trow = g_T + (t*NH + h)*TS;
        const int4*  mrow = (const int4*)(hour_mask + (size_t)n*TS);
        float wv[TS]; float sum = 0.f;
        #pragma unroll
        for (int q = 0; q < 6; q++) {
            int4   m  = __ldg(mrow + q);
            float4 uv = __ldg((const float4*)(urow + q*4));
            float4 tv = __ldg((const float4*)(trow + q*4));
            float e0 = __expf(uv.x + tv.x);
            float e1 = __expf(uv.y + tv.y);
            float e2 = __expf(uv.z + tv.z);
            float e3 = __expf(uv.w + tv.w);
            wv[4*q+0] = (m.x == 1) ? 0.f : e0;
            wv[4*q+1] = (m.y == 1) ? 0.f : e1;
            wv[4*q+2] = (m.z == 1) ? 0.f : e2;
            wv[4*q+3] = (m.w == 1) ? 0.f : e3;
            sum += (wv[4*q+0]+wv[4*q+1]) + (wv[4*q+2]+wv[4*q+3]);
        }
        const float inv = 1.f / sum;
        uint32_t w12[12];
        #pragma unroll
        for (int q = 0; q < 12; q++) {
            __half h0 = __float2half_rn(wv[2*q]*inv);
            __half h1 = __float2half_rn(wv[2*q+1]*inv);
            w12[q] = (uint32_t)__half_as_ushort(h1) << 16 | __half_as_ushort(h0);
        }
        uint4* dhp = (uint4*)(sm + FM_A + p*208 + h*48);
        dhp[0] = make_uint4(w12[0],w12[1],w12[2],w12[3]);
        dhp[1] = make_uint4(w12[4],w12[5],w12[6],w12[7]);
        dhp[2] = make_uint4(w12[8],w12[9],w12[10],w12[11]);
    }
    __syncthreads();

    // ---- mainloop (identical to R10) ----
    const int wm = wid & 3, wn = wid >> 2;
    const int grp = lane >> 2, qid = lane & 3;
    const int am = lane >> 3, r8 = lane & 7;

    const uint32_t aBase = sb + FM_A
        + (uint32_t)(wm*32 + (am & 1)*8 + r8)*208u + (uint32_t)((am >> 1) & 1)*16u;
    const uint32_t bLane = (uint32_t)(((am >> 1) & 1)*8 + r8)*208u + (uint32_t)(am & 1)*16u;

    for (int c = 0; c < 4; c++) {
        MBAR_WAIT(sb + FM_MBAR, c & 1);

        float acc[2][2][4][4];
        #pragma unroll
        for (int mt = 0; mt < 2; mt++)
            #pragma unroll
            for (int nh = 0; nh < 2; nh++)
                #pragma unroll
                for (int nt = 0; nt < 4; nt++)
                    #pragma unroll
                    for (int k = 0; k < 4; k++) acc[mt][nh][nt][k] = 0.f;

        #pragma unroll
        for (int ks = 0; ks < 6; ks++) {
            uint32_t ah[2][4];
            LDMX4(ah[0], aBase + ks*32);
            LDMX4(ah[1], aBase + ks*32 + 16*208);
            #pragma unroll
            for (int nh = 0; nh < 2; nh++) {
                const uint32_t bk = sb + FM_B + (uint32_t)(wn*64 + nh*32)*208u + bLane + ks*32;
                uint32_t bh[2][4], bl[2][4];
                LDMX4(bh[0], bk);
                LDMX4(bh[1], bk + 16*208);
                LDMX4(bl[0], bk + BL);
                LDMX4(bl[1], bk + BL + 16*208);
                #pragma unroll
                for (int mt = 0; mt < 2; mt++)
                    #pragma unroll
                    for (int nt = 0; nt < 4; nt++) {
                        const int pr = nt >> 1, sub = (nt & 1)*2;
                        MMA16816(acc[mt][nh][nt], ah[mt], bh[pr][sub], bh[pr][sub+1]);
                        MMA16816(acc[mt][nh][nt], ah[mt], bl[pr][sub], bl[pr][sub+1]);
                    }
            }
        }

        #pragma unroll
        for (int nh = 0; nh < 2; nh++)
            #pragma unroll
            for (int nt = 0; nt < 4; nt++) {
                int d = c*128 + wn*64 + nh*32 + nt*8 + qid*2;
                float bx = __ldg(b_unify + d), by = __ldg(b_unify + d + 1);
                #pragma unroll
                for (int mt = 0; mt < 2; mt++) {
                    int row = n0 + wm*32 + mt*16 + grp;
                    float2 o0 = make_float2(acc[mt][nh][nt][0] + bx, acc[mt][nh][nt][1] + by);
                    float2 o1 = make_float2(acc[mt][nh][nt][2] + bx, acc[mt][nh][nt][3] + by);
                    *(float2*)(out_emb + (size_t)row*D + d)     = o0;
                    *(float2*)(out_emb + (size_t)(row+8)*D + d) = o1;
                }
            }
        __syncthreads();
        if (tid == 0) {
            if (c < 3) {
                MBAR_EXPECT(sb + FM_MBAR, 2*BL);
                bulk_g2s(sb + FM_B,      g_Bh + (size_t)(c+1)*128*JP, BL, sb + FM_MBAR);
                bulk_g2s(sb + FM_B + BL, g_Bl + (size_t)(c+1)*128*JP, BL, sb + FM_MBAR);
            } else {
                MBAR_EXPECT(sb + FM_MBAR, 2*TLB);
                bulk_g2s(sb + FM_B,      g_Th, TLB, sb + FM_MBAR);
                bulk_g2s(sb + FM_B + BL, g_Tl, TLB, sb + FM_MBAR);
            }
        }
    }

    // ---- TL chunk (32 cols, rows 0..23 stored) ----
    MBAR_WAIT(sb + FM_MBAR, 0);
    if (wn == 0) {
        float acc[2][4][4];
        #pragma unroll
        for (int mt = 0; mt < 2; mt++)
            #pragma unroll
            for (int nt = 0; nt < 4; nt++)
                #pragma unroll
                for (int k = 0; k < 4; k++) acc[mt][nt][k] = 0.f;

        #pragma unroll
        for (int ks = 0; ks < 6; ks++) {
            uint32_t ah[2][4];
            LDMX4(ah[0], aBase + ks*32);
            LDMX4(ah[1], aBase + ks*32 + 16*208);
            const uint32_t bk = sb + FM_B + bLane + ks*32;
            uint32_t bh[2][4], bl[2][4];
            LDMX4(bh[0], bk);
            LDMX4(bh[1], bk + 16*208);
            LDMX4(bl[0], bk + BL);
            LDMX4(bl[1], bk + BL + 16*208);
            #pragma unroll
            for (int mt = 0; mt < 2; mt++)
                #pragma unroll
                for (int nt = 0; nt < 4; nt++) {
                    const int pr = nt >> 1, sub = (nt & 1)*2;
                    MMA16816(acc[mt][nt], ah[mt], bh[pr][sub], bh[pr][sub+1]);
                    MMA16816(acc[mt][nt], ah[mt], bl[pr][sub], bl[pr][sub+1]);
                }
        }
        #pragma unroll
        for (int nt = 0; nt < 3; nt++) {         // d = nt*8+qid*2 <= 22
            int d = nt*8 + qid*2;
            float bx = __ldg(b_time + d), by = __ldg(b_time + d + 1);
            #pragma unroll
            for (int mt = 0; mt < 2; mt++) {
                int row = n0 + wm*32 + mt*16 + grp;
                float2 o0 = make_float2(acc[mt][nt][0] + bx, acc[mt][nt][1] + by);
                float2 o1 = make_float2(acc[mt][nt][2] + bx, acc[mt][nt][3] + by);
                *(float2*)(out_tl + (size_t)row*TS + d)     = o0;
                *(float2*)(out_tl + (size_t)(row+8)*TS + d) = o1;
            }
        }
    }
}

// ---------------- launch ----------------
extern "C" void kernel_launch(void* const* d_in, const int* in_sizes, int n_in,
                              void* d_out, int out_size)
{
    const float* ts_emb    = (const float*)d_in[0];
    const int*   user_x    = (const int*)  d_in[3];
    const int*   hour_x    = (const int*)  d_in[4];
    const int*   hour_mask = (const int*)  d_in[5];
    const float* upt       = (const float*)d_in[6];
    const float* Wq        = (const float*)d_in[7];
    const float* bq        = (const float*)d_in[8];
    const float* Wk        = (const float*)d_in[9];
    const float* bk        = (const float*)d_in[10];
    const float* Wv        = (const float*)d_in[11];
    const float* bv        = (const float*)d_in[12];
    const float* Wu        = (const float*)d_in[13];
    const float* bu        = (const float*)d_in[14];
    const float* Wt        = (const float*)d_in[15];
    const float* bt        = (const float*)d_in[16];

    float* out_emb = (float*)d_out;
    float* out_tl  = out_emb + (size_t)NPOS * D;

    cudaFuncSetAttribute(k_main, cudaFuncAttributeMaxDynamicSharedMemorySize, FM_TOTAL);

    k_pre1<<<1088, 256>>>(ts_emb, user_x, upt, Wq, bq, Wk, bk, Wv, bv);
    k_pre23<<<936, 256>>>(Wu, Wt);
    k_main<<<256, 256, FM_TOTAL>>>(hour_x, hour_mask, bu, bt, out_emb, out_tl);
}

// round 14
// speedup vs baseline: 2.1482x; 1.0115x over previous
#include <cuda_runtime.h>
#include <cuda_fp16.h>
#include <math.h>
#include <stdint.h>

#define NH 4
#define HD 128
#define D  512
#define TS 24
#define NB 64
#define NPOS 32768
#define J   96
#define JP  104
#define BL  26624     /* bytes per B chunk (128 rows x 208B, hi only) */
#define TLB 6656      /* TL chunk (32 rows x 208B) */
#define SCALE 0.08838834764831845f

// ---------------- device scratch ----------------
__device__ __align__(16)  float g_A [NB*NH*HD];
__device__ __align__(16)  float g_Bq[TS*NH*HD];
__device__ __align__(16)  float g_K [TS*NH*HD];
__device__ __align__(16)  float g_V [TS*NH*HD];
__device__ __align__(16)  float g_U [NB*NH*TS];
__device__ __align__(16)  float g_T [TS*NH*TS];
__device__ __align__(128) __half g_Bh[D*JP];      // VU^T fp16: [d][j], 208B rows
__device__ __align__(128) __half g_Th[32*JP];     // TL fp16 (rows 24..31 zero)

// ---------------- helpers ----------------
__device__ __forceinline__ uint32_t smem_u32(const void* p){
    uint32_t a;
    asm("{ .reg .u64 t; cvta.to.shared.u64 t, %1; cvt.u32.u64 %0, t; }" : "=r"(a) : "l"(p));
    return a;
}
__device__ __forceinline__ void bulk_g2s(uint32_t dst, const void* src,
                                         uint32_t bytes, uint32_t mbar){
    asm volatile(
        "cp.async.bulk.shared::cluster.global.mbarrier::complete_tx::bytes [%0], [%1], %2, [%3];"
        :: "r"(dst), "l"(src), "r"(bytes), "r"(mbar) : "memory");
}
#define MBAR_INIT(a, c)  asm volatile("mbarrier.init.shared.b64 [%0], %1;" :: "r"(a), "r"(c) : "memory")
#define MBAR_EXPECT(a,b) asm volatile("mbarrier.arrive.expect_tx.shared.b64 _, [%0], %1;" :: "r"(a), "r"(b) : "memory")
#define MBAR_WAIT(a, ph) do { \
    uint32_t _m=(a), _p=(ph), _d; \
    asm volatile("{\n\t.reg .pred p;\n\t" \
        "mbarrier.try_wait.parity.acquire.cta.shared::cta.b64 p, [%1], %2;\n\t" \
        "selp.b32 %0, 1, 0, p;\n\t}" : "=r"(_d) : "r"(_m), "r"(_p) : "memory"); \
    if (!_d) { asm volatile("{\n\t.reg .pred P1;\n\t" \
        "W_%=:\n\tmbarrier.try_wait.parity.acquire.cta.shared::cta.b64 P1, [%0], %1, 0x989680;\n\t" \
        "@P1 bra.uni WD_%=;\n\tbra.uni W_%=;\n\tWD_%=:\n\t}" :: "r"(_m), "r"(_p) : "memory"); } \
} while(0)

#define MMA16816(c, a, b0v, b1v) \
    asm volatile("mma.sync.aligned.m16n8k16.row.col.f32.f16.f16.f32 " \
        "{%0,%1,%2,%3}, {%4,%5,%6,%7}, {%8,%9}, {%0,%1,%2,%3};" \
        : "+f"((c)[0]), "+f"((c)[1]), "+f"((c)[2]), "+f"((c)[3]) \
        : "r"((a)[0]), "r"((a)[1]), "r"((a)[2]), "r"((a)[3]), \
          "r"(b0v), "r"(b1v))

#define LDMX4(r, addr) \
    asm volatile("ldmatrix.sync.aligned.m8n8.x4.shared.b16 {%0,%1,%2,%3}, [%4];" \
        : "=r"((r)[0]), "=r"((r)[1]), "=r"((r)[2]), "=r"((r)[3]) : "r"(addr))

__device__ __forceinline__ float wredsum(float v){
    #pragma unroll
    for (int o = 16; o; o >>= 1) v += __shfl_xor_sync(0xFFFFFFFFu, v, o);
    return v;
}
__device__ __forceinline__ float dot4(float4 a, float4 b){
    return fmaf(a.x,b.x, fmaf(a.y,b.y, fmaf(a.z,b.z, a.w*b.w)));
}

// ---------------- K1: A (8 rows/warp) + Bq/K/V (24 rows/warp) ----------------
// rowgroups: 0..7 = A user groups; 8 = Bq; 9 = K; 10 = V.  grid = 11*64 = 704
__global__ void __launch_bounds__(256)
k_pre1(const float* __restrict__ ts_emb, const int* __restrict__ user_x,
       const float* __restrict__ upt,
       const float* __restrict__ Wq, const float* __restrict__ bq,
       const float* __restrict__ Wk, const float* __restrict__ bk,
       const float* __restrict__ Wv, const float* __restrict__ bv)
{
    const int wid  = threadIdx.x >> 5;
    const int lane = threadIdx.x & 31;
    const int rg   = blockIdx.x >> 6;
    const int he   = (blockIdx.x & 63)*8 + wid;

    if (rg < 8) {
        const float* w = Wq + (size_t)he*1024;
        const float* x[8];
        #pragma unroll
        for (int i = 0; i < 8; i++)
            x[i] = upt + (size_t)__ldg(user_x + rg*8 + i)*D;
        float acc[8] = {0,0,0,0,0,0,0,0};
        #pragma unroll
        for (int ch = 0; ch < 4; ch++) {
            int e = ch*128 + lane*4;
            float4 w4 = __ldg((const float4*)(w + e));
            #pragma unroll
            for (int i = 0; i < 8; i++) {
                float4 x4 = __ldg((const float4*)(x[i] + e));
                acc[i] = fmaf(w4.x,x4.x, fmaf(w4.y,x4.y, fmaf(w4.z,x4.z, fmaf(w4.w,x4.w, acc[i]))));
            }
        }
        float r = 0.f;
        #pragma unroll
        for (int i = 0; i < 8; i++) {
            float s = wredsum(acc[i]);
            if (lane == i) r = s;
        }
        if (lane < 8)
            g_A[(size_t)(rg*8 + lane)*D + he] = r;
    } else {
        const float* w;
        float bias;
        float* dst;
        if (rg == 8)      { w = Wq + (size_t)he*1024 + 512; bias = __ldg(bq + he); dst = g_Bq; }
        else if (rg == 9) { w = Wk + (size_t)he*512;        bias = __ldg(bk + he); dst = g_K; }
        else              { w = Wv + (size_t)he*512;        bias = __ldg(bv + he); dst = g_V; }

        float acc[24];
        #pragma unroll
        for (int i = 0; i < 24; i++) acc[i] = 0.f;
        #pragma unroll
        for (int ch = 0; ch < 4; ch++) {
            int e = ch*128 + lane*4;
            float4 w4 = __ldg((const float4*)(w + e));
            #pragma unroll
            for (int i = 0; i < 24; i++) {
                float4 x4 = __ldg((const float4*)(ts_emb + i*D + e));
                acc[i] = fmaf(w4.x,x4.x, fmaf(w4.y,x4.y, fmaf(w4.z,x4.z, fmaf(w4.w,x4.w, acc[i]))));
            }
        }
        float r = 0.f;
        #pragma unroll
        for (int i = 0; i < 24; i++) {
            float s = wredsum(acc[i]);
            if (lane == i) r = s;
        }
        if (lane < 24)
            dst[(size_t)lane*D + he] = r + bias;
    }
}

// ---------------- K23: VU/TL folds (fp16) + U/T score tables ----------------
__global__ void __launch_bounds__(256)
k_pre23(const float* __restrict__ Wu, const float* __restrict__ Wt)
{
    const int wid  = threadIdx.x >> 5;
    const int lane = threadIdx.x & 31;
    if (blockIdx.x < 804) {
        int task = blockIdx.x*8 + wid;
        if (task < 6144) {
            int j  = task >> 6;
            int dg = task & 63;
            int h = j / TS, k = j - h*TS;
            float4 vr = *(const float4*)(g_V + (size_t)k*D + h*HD + lane*4);
            const float* wbase = Wu + h*HD + lane*4;
            float val = 0.f;
            #pragma unroll
            for (int dd = 0; dd < 8; dd++) {
                int d = dg*8 + dd;
                float4 w4 = __ldg((const float4*)(wbase + (size_t)d*D));
                float s = wredsum(dot4(vr, w4));
                if (lane == dd) val = s;
            }
            if (lane < 8)
                g_Bh[(size_t)(dg*8 + lane)*JP + j] = __float2half_rn(val);
        } else if (task < 6432) {
            int t2 = task - 6144;
            int j  = t2 / 3;
            int dg = t2 - j*3;
            int h = j / TS, k = j - h*TS;
            float4 vr = *(const float4*)(g_V + (size_t)k*D + h*HD + lane*4);
            const float* wbase = Wt + h*HD + lane*4;
            float val = 0.f;
            #pragma unroll
            for (int dd = 0; dd < 8; dd++) {
                int d = dg*8 + dd;
                float4 w4 = __ldg((const float4*)(wbase + (size_t)d*D));
                float s = wredsum(dot4(vr, w4));
                if (lane == dd) val = s;
            }
            if (lane < 8)
                g_Th[(size_t)(dg*8 + lane)*JP + j] = __float2half_rn(val);
        }
    } else {
        int task = (blockIdx.x - 804)*8 + wid;
        if (task < 768) {
            int b   = task / 12;
            int rem = task - b*12;
            int h   = rem / 3;
            int kg  = rem - h*3;
            float4 av = *(const float4*)(g_A + (size_t)b*D + h*HD + lane*4);
            float val = 0.f;
            #pragma unroll
            for (int dd = 0; dd < 8; dd++) {
                int k = kg*8 + dd;
                float4 kv = *(const float4*)(g_K + (size_t)k*D + h*HD + lane*4);
                float s = wredsum(dot4(av, kv));
                if (lane == dd) val = s;
            }
            if (lane < 8)
                g_U[(b*NH + h)*TS + kg*8 + lane] = val * SCALE;
        } else if (task < 1056) {
            int t2  = task - 768;
            int t   = t2 / 12;
            int rem = t2 - t*12;
            int h   = rem / 3;
            int kg  = rem - h*3;
            float4 bv = *(const float4*)(g_Bq + (size_t)t*D + h*HD + lane*4);
            float val = 0.f;
            #pragma unroll
            for (int dd = 0; dd < 8; dd++) {
                int k = kg*8 + dd;
                float4 kv = *(const float4*)(g_K + (size_t)k*D + h*HD + lane*4);
                float s = wredsum(dot4(bv, kv));
                if (lane == dd) val = s;
            }
            if (lane < 8)
                g_T[(t*NH + h)*TS + kg*8 + lane] = val * SCALE;
        }
    }
}

// ---------------- k_main: softmax + A fp16 + 1-pass double-buffered HMMA ----------------
#define FM_A     128               /* A tile: 128 x 208B = 26624 */
#define FM_B0    26752
#define FM_B1    53376
#define FM_TOTAL 80000

__global__ void __launch_bounds__(256, 2)
k_main(const int* __restrict__ hour_x, const int* __restrict__ hour_mask,
       const float* __restrict__ b_unify, const float* __restrict__ b_time,
       float* __restrict__ out_emb, float* __restrict__ out_tl)
{
    extern __shared__ char sm[];
    const uint32_t sb = smem_u32(sm);
    const int tid  = threadIdx.x;
    const int wid  = tid >> 5;
    const int lane = tid & 31;
    const int n0   = blockIdx.x * 128;

    // prologue: chunks 0,1 into buf0,buf1
    if (tid == 0) {
        MBAR_INIT(sb + 0, 1);
        MBAR_INIT(sb + 8, 1);
        MBAR_EXPECT(sb + 0, BL);
        bulk_g2s(sb + FM_B0, g_Bh, BL, sb + 0);
        MBAR_EXPECT(sb + 8, BL);
        bulk_g2s(sb + FM_B1, g_Bh + (size_t)128*JP, BL, sb + 8);
    }

    // ---- softmax from U+T (inline exp) -> A fp16 tile ----
    const int bb = n0 >> 9;
    #pragma unroll
    for (int r = 0; r < 2; r++) {
        const int task = r*256 + tid;
        const int p = task & 127;
        const int h = task >> 7;
        const int n = n0 + p;
        const int t = __ldg(hour_x + n);
        const float* urow = g_U + (bb*NH + h)*TS;
        const float* trow = g_T + (t*NH + h)*TS;
        const int4*  mrow = (const int4*)(hour_mask + (size_t)n*TS);
        float wv[TS]; float sum = 0.f;
        #pragma unroll
        for (int q = 0; q < 6; q++) {
            int4   m  = __ldg(mrow + q);
            float4 uv = __ldg((const float4*)(urow + q*4));
            float4 tv = __ldg((const float4*)(trow + q*4));
            float e0 = __expf(uv.x + tv.x);
            float e1 = __expf(uv.y + tv.y);
            float e2 = __expf(uv.z + tv.z);
            float e3 = __expf(uv.w + tv.w);
            wv[4*q+0] = (m.x == 1) ? 0.f : e0;
            wv[4*q+1] = (m.y == 1) ? 0.f : e1;
            wv[4*q+2] = (m.z == 1) ? 0.f : e2;
            wv[4*q+3] = (m.w == 1) ? 0.f : e3;
            sum += (wv[4*q+0]+wv[4*q+1]) + (wv[4*q+2]+wv[4*q+3]);
        }
        const float inv = 1.f / sum;
        uint32_t w12[12];
        #pragma unroll
        for (int q = 0; q < 12; q++) {
            __half h0 = __float2half_rn(wv[2*q]*inv);
            __half h1 = __float2half_rn(wv[2*q+1]*inv);
            w12[q] = (uint32_t)__half_as_ushort(h1) << 16 | __half_as_ushort(h0);
        }
        uint4* dhp = (uint4*)(sm + FM_A + p*208 + h*48);
        dhp[0] = make_uint4(w12[0],w12[1],w12[2],w12[3]);
        dhp[1] = make_uint4(w12[4],w12[5],w12[6],w12[7]);
        dhp[2] = make_uint4(w12[8],w12[9],w12[10],w12[11]);
    }
    __syncthreads();

    const int wm = wid & 3, wn = wid >> 2;
    const int grp = lane >> 2, qid = lane & 3;
    const int am = lane >> 3, r8 = lane & 7;

    const uint32_t aBase = sb + FM_A
        + (uint32_t)(wm*32 + (am & 1)*8 + r8)*208u + (uint32_t)((am >> 1) & 1)*16u;
    const uint32_t bLane = (uint32_t)(((am >> 1) & 1)*8 + r8)*208u + (uint32_t)(am & 1)*16u;

    // ---- mainloop: 5 chunks (4 B + TL), double-buffered ----
    for (int c = 0; c <= 4; c++) {
        const uint32_t buf = sb + ((c & 1) ? FM_B1 : FM_B0);
        MBAR_WAIT(sb + 8*(c & 1), (c >> 1) & 1);

        float acc[2][2][4][4];
        #pragma unroll
        for (int mt = 0; mt < 2; mt++)
            #pragma unroll
            for (int nh = 0; nh < 2; nh++)
                #pragma unroll
                for (int nt = 0; nt < 4; nt++)
                    #pragma unroll
                    for (int k = 0; k < 4; k++) acc[mt][nh][nt][k] = 0.f;

        if (c < 4) {
            #pragma unroll
            for (int ks = 0; ks < 6; ks++) {
                uint32_t ah[2][4];
                LDMX4(ah[0], aBase + ks*32);
                LDMX4(ah[1], aBase + ks*32 + 16*208);
                #pragma unroll
                for (int nh = 0; nh < 2; nh++) {
                    const uint32_t bk = buf + (uint32_t)(wn*64 + nh*32)*208u + bLane + ks*32;
                    uint32_t bh[2][4];
                    LDMX4(bh[0], bk);
                    LDMX4(bh[1], bk + 16*208);
                    #pragma unroll
                    for (int mt = 0; mt < 2; mt++)
                        #pragma unroll
                        for (int nt = 0; nt < 4; nt++) {
                            const int pr = nt >> 1, sub = (nt & 1)*2;
                            MMA16816(acc[mt][nh][nt], ah[mt], bh[pr][sub], bh[pr][sub+1]);
                        }
                }
            }
        } else if (wn == 0) {
            #pragma unroll
            for (int ks = 0; ks < 6; ks++) {
                uint32_t ah[2][4];
                LDMX4(ah[0], aBase + ks*32);
                LDMX4(ah[1], aBase + ks*32 + 16*208);
                const uint32_t bk = buf + bLane + ks*32;
                uint32_t bh[2][4];
                LDMX4(bh[0], bk);
                LDMX4(bh[1], bk + 16*208);
                #pragma unroll
                for (int mt = 0; mt < 2; mt++)
                    #pragma unroll
                    for (int nt = 0; nt < 4; nt++) {
                        const int pr = nt >> 1, sub = (nt & 1)*2;
                        MMA16816(acc[mt][0][nt], ah[mt], bh[pr][sub], bh[pr][sub+1]);
                    }
            }
        }
        __syncthreads();
        if (tid == 0 && c + 2 <= 4) {
            const int nc = c + 2;
            const uint32_t mb = sb + 8*(c & 1);
            if (nc < 4) {
                MBAR_EXPECT(mb, BL);
                bulk_g2s(buf, g_Bh + (size_t)nc*128*JP, BL, mb);
            } else {
                MBAR_EXPECT(mb, TLB);
                bulk_g2s(buf, g_Th, TLB, mb);
            }
        }

        // epilogue stores (after sync so next load overlaps them)
        if (c < 4) {
            #pragma unroll
            for (int nh = 0; nh < 2; nh++)
                #pragma unroll
                for (int nt = 0; nt < 4; nt++) {
                    int d = c*128 + wn*64 + nh*32 + nt*8 + qid*2;
                    float bx = __ldg(b_unify + d), by = __ldg(b_unify + d + 1);
                    #pragma unroll
                    for (int mt = 0; mt < 2; mt++) {
                        int row = n0 + wm*32 + mt*16 + grp;
                        float2 o0 = make_float2(acc[mt][nh][nt][0] + bx, acc[mt][nh][nt][1] + by);
                        float2 o1 = make_float2(acc[mt][nh][nt][2] + bx, acc[mt][nh][nt][3] + by);
                        *(float2*)(out_emb + (size_t)row*D + d)     = o0;
                        *(float2*)(out_emb + (size_t)(row+8)*D + d) = o1;
                    }
                }
        } else if (wn == 0) {
            #pragma unroll
            for (int nt = 0; nt < 3; nt++) {     // d <= 22
                int d = nt*8 + qid*2;
                float bx = __ldg(b_time + d), by = __ldg(b_time + d + 1);
                #pragma unroll
                for (int mt = 0; mt < 2; mt++) {
                    int row = n0 + wm*32 + mt*16 + grp;
                    float2 o0 = make_float2(acc[mt][0][nt][0] + bx, acc[mt][0][nt][1] + by);
                    float2 o1 = make_float2(acc[mt][0][nt][2] + bx, acc[mt][0][nt][3] + by);
                    *(float2*)(out_tl + (size_t)row*TS + d)     = o0;
                    *(float2*)(out_tl + (size_t)(row+8)*TS + d) = o1;
                }
            }
        }
    }
}

// ---------------- launch ----------------
extern "C" void kernel_launch(void* const* d_in, const int* in_sizes, int n_in,
                              void* d_out, int out_size)
{
    const float* ts_emb    = (const float*)d_in[0];
    const int*   user_x    = (const int*)  d_in[3];
    const int*   hour_x    = (const int*)  d_in[4];
    const int*   hour_mask = (const int*)  d_in[5];
    const float* upt       = (const float*)d_in[6];
    const float* Wq        = (const float*)d_in[7];
    const float* bq        = (const float*)d_in[8];
    const float* Wk        = (const float*)d_in[9];
    const float* bk        = (const float*)d_in[10];
    const float* Wv        = (const float*)d_in[11];
    const float* bv        = (const float*)d_in[12];
    const float* Wu        = (const float*)d_in[13];
    const float* bu        = (const float*)d_in[14];
    const float* Wt        = (const float*)d_in[15];
    const float* bt        = (const float*)d_in[16];

    float* out_emb = (float*)d_out;
    float* out_tl  = out_emb + (size_t)NPOS * D;

    cudaFuncSetAttribute(k_main, cudaFuncAttributeMaxDynamicSharedMemorySize, FM_TOTAL);

    k_pre1<<<704, 256>>>(ts_emb, user_x, upt, Wq, bq, Wk, bk, Wv, bv);
    k_pre23<<<936, 256>>>(Wu, Wt);
    k_main<<<256, 256, FM_TOTAL>>>(hour_x, hour_mask, bu, bt, out_emb, out_tl);
}

// round 15
// speedup vs baseline: 2.4386x; 1.1352x over previous
#include <cuda_runtime.h>
#include <cuda_fp16.h>
#include <math.h>
#include <stdint.h>

#define NH 4
#define HD 128
#define D  512
#define TS 24
#define NB 64
#define NPOS 32768
#define J   96
#define JP  104
#define BL  26624     /* bytes per B chunk (128 rows x 208B, fp16) */
#define TLB 6656      /* TL chunk (32 rows x 208B) */
#define SCALE 0.08838834764831845f

// ---------------- device scratch ----------------
__device__ __align__(16)  float g_A [NB*NH*HD];
__device__ __align__(16)  float g_Bq[TS*NH*HD];
__device__ __align__(16)  float g_K [TS*NH*HD];
__device__ __align__(16)  float g_V [TS*NH*HD];
__device__ __align__(16)  float g_U [NB*NH*TS];
__device__ __align__(16)  float g_T [TS*NH*TS];
__device__ __align__(128) __half g_Bh[D*JP];      // VU^T fp16: [d][j], 208B rows
__device__ __align__(128) __half g_Th[32*JP];     // TL fp16 (rows 24..31 zero)

// ---------------- helpers ----------------
__device__ __forceinline__ uint32_t smem_u32(const void* p){
    uint32_t a;
    asm("{ .reg .u64 t; cvta.to.shared.u64 t, %1; cvt.u32.u64 %0, t; }" : "=r"(a) : "l"(p));
    return a;
}
__device__ __forceinline__ void bulk_g2s(uint32_t dst, const void* src,
                                         uint32_t bytes, uint32_t mbar){
    asm volatile(
        "cp.async.bulk.shared::cluster.global.mbarrier::complete_tx::bytes [%0], [%1], %2, [%3];"
        :: "r"(dst), "l"(src), "r"(bytes), "r"(mbar) : "memory");
}
#define MBAR_INIT(a, c)  asm volatile("mbarrier.init.shared.b64 [%0], %1;" :: "r"(a), "r"(c) : "memory")
#define MBAR_EXPECT(a,b) asm volatile("mbarrier.arrive.expect_tx.shared.b64 _, [%0], %1;" :: "r"(a), "r"(b) : "memory")
#define MBAR_WAIT(a, ph) do { \
    uint32_t _m=(a), _p=(ph), _d; \
    asm volatile("{\n\t.reg .pred p;\n\t" \
        "mbarrier.try_wait.parity.acquire.cta.shared::cta.b64 p, [%1], %2;\n\t" \
        "selp.b32 %0, 1, 0, p;\n\t}" : "=r"(_d) : "r"(_m), "r"(_p) : "memory"); \
    if (!_d) { asm volatile("{\n\t.reg .pred P1;\n\t" \
        "W_%=:\n\tmbarrier.try_wait.parity.acquire.cta.shared::cta.b64 P1, [%0], %1, 0x989680;\n\t" \
        "@P1 bra.uni WD_%=;\n\tbra.uni W_%=;\n\tWD_%=:\n\t}" :: "r"(_m), "r"(_p) : "memory"); } \
} while(0)

#define MMA16816(c, a, b0v, b1v) \
    asm volatile("mma.sync.aligned.m16n8k16.row.col.f32.f16.f16.f32 " \
        "{%0,%1,%2,%3}, {%4,%5,%6,%7}, {%8,%9}, {%0,%1,%2,%3};" \
        : "+f"((c)[0]), "+f"((c)[1]), "+f"((c)[2]), "+f"((c)[3]) \
        : "r"((a)[0]), "r"((a)[1]), "r"((a)[2]), "r"((a)[3]), \
          "r"(b0v), "r"(b1v))

#define LDMX4(r, addr) \
    asm volatile("ldmatrix.sync.aligned.m8n8.x4.shared.b16 {%0,%1,%2,%3}, [%4];" \
        : "=r"((r)[0]), "=r"((r)[1]), "=r"((r)[2]), "=r"((r)[3]) : "r"(addr))

__device__ __forceinline__ float wredsum(float v){
    #pragma unroll
    for (int o = 16; o; o >>= 1) v += __shfl_xor_sync(0xFFFFFFFFu, v, o);
    return v;
}
__device__ __forceinline__ float dot4(float4 a, float4 b){
    return fmaf(a.x,b.x, fmaf(a.y,b.y, fmaf(a.z,b.z, a.w*b.w)));
}

// ---------------- K1: A, Bq, K, V (R13 version — proven fastest) ----------------
__global__ void __launch_bounds__(256)
k_pre1(const float* __restrict__ ts_emb, const int* __restrict__ user_x,
       const float* __restrict__ upt,
       const float* __restrict__ Wq, const float* __restrict__ bq,
       const float* __restrict__ Wk, const float* __restrict__ bk,
       const float* __restrict__ Wv, const float* __restrict__ bv)
{
    const int wid  = threadIdx.x >> 5;
    const int lane = threadIdx.x & 31;
    const int rg   = blockIdx.x >> 6;
    const int he   = (blockIdx.x & 63)*8 + wid;

    const float* w;
    const float* x[8];
    float bias = 0.f;
    float* dst;
    int row0;
    if (rg < 8) {
        w = Wq + (size_t)he*1024; dst = g_A; row0 = rg*8;
        #pragma unroll
        for (int i = 0; i < 8; i++)
            x[i] = upt + (size_t)__ldg(user_x + rg*8 + i)*D;
    } else if (rg < 11) {
        int g = rg - 8;
        w = Wq + (size_t)he*1024 + 512; bias = __ldg(bq + he);
        dst = g_Bq; row0 = g*8;
        #pragma unroll
        for (int i = 0; i < 8; i++) x[i] = ts_emb + (g*8 + i)*D;
    } else if (rg < 14) {
        int g = rg - 11;
        w = Wk + (size_t)he*512; bias = __ldg(bk + he);
        dst = g_K; row0 = g*8;
        #pragma unroll
        for (int i = 0; i < 8; i++) x[i] = ts_emb + (g*8 + i)*D;
    } else {
        int g = rg - 14;
        w = Wv + (size_t)he*512; bias = __ldg(bv + he);
        dst = g_V; row0 = g*8;
        #pragma unroll
        for (int i = 0; i < 8; i++) x[i] = ts_emb + (g*8 + i)*D;
    }

    float acc[8] = {0,0,0,0,0,0,0,0};
    #pragma unroll
    for (int ch = 0; ch < 4; ch++) {
        int e = ch*128 + lane*4;
        float4 w4 = __ldg((const float4*)(w + e));
        #pragma unroll
        for (int i = 0; i < 8; i++) {
            float4 x4 = __ldg((const float4*)(x[i] + e));
            acc[i] = fmaf(w4.x,x4.x, fmaf(w4.y,x4.y, fmaf(w4.z,x4.z, fmaf(w4.w,x4.w, acc[i]))));
        }
    }
    float r = 0.f;
    #pragma unroll
    for (int i = 0; i < 8; i++) {
        float s = wredsum(acc[i]);
        if (lane == i) r = s;
    }
    if (lane < 8)
        dst[(size_t)(row0 + lane)*D + he] = r + bias;
}

// ---------------- K23: VU/TL folds (fp16) + U/T score tables ----------------
__global__ void __launch_bounds__(256)
k_pre23(const float* __restrict__ Wu, const float* __restrict__ Wt)
{
    const int wid  = threadIdx.x >> 5;
    const int lane = threadIdx.x & 31;
    if (blockIdx.x < 804) {
        int task = blockIdx.x*8 + wid;
        if (task < 6144) {
            int j  = task >> 6;
            int dg = task & 63;
            int h = j / TS, k = j - h*TS;
            float4 vr = *(const float4*)(g_V + (size_t)k*D + h*HD + lane*4);
            const float* wbase = Wu + h*HD + lane*4;
            float val = 0.f;
            #pragma unroll
            for (int dd = 0; dd < 8; dd++) {
                int d = dg*8 + dd;
                float4 w4 = __ldg((const float4*)(wbase + (size_t)d*D));
                float s = wredsum(dot4(vr, w4));
                if (lane == dd) val = s;
            }
            if (lane < 8)
                g_Bh[(size_t)(dg*8 + lane)*JP + j] = __float2half_rn(val);
        } else if (task < 6432) {
            int t2 = task - 6144;
            int j  = t2 / 3;
            int dg = t2 - j*3;
            int h = j / TS, k = j - h*TS;
            float4 vr = *(const float4*)(g_V + (size_t)k*D + h*HD + lane*4);
            const float* wbase = Wt + h*HD + lane*4;
            float val = 0.f;
            #pragma unroll
            for (int dd = 0; dd < 8; dd++) {
                int d = dg*8 + dd;
                float4 w4 = __ldg((const float4*)(wbase + (size_t)d*D));
                float s = wredsum(dot4(vr, w4));
                if (lane == dd) val = s;
            }
            if (lane < 8)
                g_Th[(size_t)(dg*8 + lane)*JP + j] = __float2half_rn(val);
        }
    } else {
        int task = (blockIdx.x - 804)*8 + wid;
        if (task < 768) {
            int b   = task / 12;
            int rem = task - b*12;
            int h   = rem / 3;
            int kg  = rem - h*3;
            float4 av = *(const float4*)(g_A + (size_t)b*D + h*HD + lane*4);
            float val = 0.f;
            #pragma unroll
            for (int dd = 0; dd < 8; dd++) {
                int k = kg*8 + dd;
                float4 kv = *(const float4*)(g_K + (size_t)k*D + h*HD + lane*4);
                float s = wredsum(dot4(av, kv));
                if (lane == dd) val = s;
            }
            if (lane < 8)
                g_U[(b*NH + h)*TS + kg*8 + lane] = val * SCALE;
        } else if (task < 1056) {
            int t2  = task - 768;
            int t   = t2 / 12;
            int rem = t2 - t*12;
            int h   = rem / 3;
            int kg  = rem - h*3;
            float4 bv = *(const float4*)(g_Bq + (size_t)t*D + h*HD + lane*4);
            float val = 0.f;
            #pragma unroll
            for (int dd = 0; dd < 8; dd++) {
                int k = kg*8 + dd;
                float4 kv = *(const float4*)(g_K + (size_t)k*D + h*HD + lane*4);
                float s = wredsum(dot4(bv, kv));
                if (lane == dd) val = s;
            }
            if (lane < 8)
                g_T[(t*NH + h)*TS + kg*8 + lane] = val * SCALE;
        }
    }
}

// ---------------- k_main: softmax + A fp16 + 1-pass double-buffered HMMA ----------------
#define FM_A     128               /* A tile: 128 x 208B = 26624 */
#define FM_B0    26752
#define FM_B1    53376
#define FM_TOTAL 80000

__global__ void __launch_bounds__(256, 2)
k_main(const int* __restrict__ hour_x, const int* __restrict__ hour_mask,
       const float* __restrict__ b_unify, const float* __restrict__ b_time,
       float* __restrict__ out_emb, float* __restrict__ out_tl)
{
    extern __shared__ char sm[];
    const uint32_t sb = smem_u32(sm);
    const int tid  = threadIdx.x;
    const int wid  = tid >> 5;
    const int lane = tid & 31;
    const int n0   = blockIdx.x * 128;

    // prologue: chunks 0,1 into buf0,buf1
    if (tid == 0) {
        MBAR_INIT(sb + 0, 1);
        MBAR_INIT(sb + 8, 1);
        MBAR_EXPECT(sb + 0, BL);
        bulk_g2s(sb + FM_B0, g_Bh, BL, sb + 0);
        MBAR_EXPECT(sb + 8, BL);
        bulk_g2s(sb + FM_B1, g_Bh + (size_t)128*JP, BL, sb + 8);
    }

    // ---- softmax from U+T (inline exp) -> A fp16 tile ----
    const int bb = n0 >> 9;
    #pragma unroll
    for (int r = 0; r < 2; r++) {
        const int task = r*256 + tid;
        const int p = task & 127;
        const int h = task >> 7;
        const int n = n0 + p;
        const int t = __ldg(hour_x + n);
        const float* urow = g_U + (bb*NH + h)*TS;
        const float* trow = g_T + (t*NH + h)*TS;
        const int4*  mrow = (const int4*)(hour_mask + (size_t)n*TS);
        float wv[TS]; float sum = 0.f;
        #pragma unroll
        for (int q = 0; q < 6; q++) {
            int4   m  = __ldg(mrow + q);
            float4 uv = __ldg((const float4*)(urow + q*4));
            float4 tv = __ldg((const float4*)(trow + q*4));
            float e0 = __expf(uv.x + tv.x);
            float e1 = __expf(uv.y + tv.y);
            float e2 = __expf(uv.z + tv.z);
            float e3 = __expf(uv.w + tv.w);
            wv[4*q+0] = (m.x == 1) ? 0.f : e0;
            wv[4*q+1] = (m.y == 1) ? 0.f : e1;
            wv[4*q+2] = (m.z == 1) ? 0.f : e2;
            wv[4*q+3] = (m.w == 1) ? 0.f : e3;
            sum += (wv[4*q+0]+wv[4*q+1]) + (wv[4*q+2]+wv[4*q+3]);
        }
        const float inv = 1.f / sum;
        uint32_t w12[12];
        #pragma unroll
        for (int q = 0; q < 12; q++) {
            __half h0 = __float2half_rn(wv[2*q]*inv);
            __half h1 = __float2half_rn(wv[2*q+1]*inv);
            w12[q] = (uint32_t)__half_as_ushort(h1) << 16 | __half_as_ushort(h0);
        }
        uint4* dhp = (uint4*)(sm + FM_A + p*208 + h*48);
        dhp[0] = make_uint4(w12[0],w12[1],w12[2],w12[3]);
        dhp[1] = make_uint4(w12[4],w12[5],w12[6],w12[7]);
        dhp[2] = make_uint4(w12[8],w12[9],w12[10],w12[11]);
    }
    __syncthreads();

    const int wm = wid & 3, wn = wid >> 2;
    const int grp = lane >> 2, qid = lane & 3;
    const int am = lane >> 3, r8 = lane & 7;

    const uint32_t aBase = sb + FM_A
        + (uint32_t)(wm*32 + (am & 1)*8 + r8)*208u + (uint32_t)((am >> 1) & 1)*16u;
    const uint32_t bLane = (uint32_t)(((am >> 1) & 1)*8 + r8)*208u + (uint32_t)(am & 1)*16u;

    // ---- mainloop: 5 chunks (4 B + TL), double-buffered ----
    for (int c = 0; c <= 4; c++) {
        const uint32_t buf = sb + ((c & 1) ? FM_B1 : FM_B0);
        MBAR_WAIT(sb + 8*(c & 1), (c >> 1) & 1);

        float acc[2][2][4][4];
        #pragma unroll
        for (int mt = 0; mt < 2; mt++)
            #pragma unroll
            for (int nh = 0; nh < 2; nh++)
                #pragma unroll
                for (int nt = 0; nt < 4; nt++)
                    #pragma unroll
                    for (int k = 0; k < 4; k++) acc[mt][nh][nt][k] = 0.f;

        if (c < 4) {
            #pragma unroll
            for (int ks = 0; ks < 6; ks++) {
                uint32_t ah[2][4];
                LDMX4(ah[0], aBase + ks*32);
                LDMX4(ah[1], aBase + ks*32 + 16*208);
                #pragma unroll
                for (int nh = 0; nh < 2; nh++) {
                    const uint32_t bk = buf + (uint32_t)(wn*64 + nh*32)*208u + bLane + ks*32;
                    uint32_t bh[2][4];
                    LDMX4(bh[0], bk);
                    LDMX4(bh[1], bk + 16*208);
                    #pragma unroll
                    for (int mt = 0; mt < 2; mt++)
                        #pragma unroll
                        for (int nt = 0; nt < 4; nt++) {
                            const int pr = nt >> 1, sub = (nt & 1)*2;
                            MMA16816(acc[mt][nh][nt], ah[mt], bh[pr][sub], bh[pr][sub+1]);
                        }
                }
            }
        } else if (wn == 0) {
            #pragma unroll
            for (int ks = 0; ks < 6; ks++) {
                uint32_t ah[2][4];
                LDMX4(ah[0], aBase + ks*32);
                LDMX4(ah[1], aBase + ks*32 + 16*208);
                const uint32_t bk = buf + bLane + ks*32;
                uint32_t bh[2][4];
                LDMX4(bh[0], bk);
                LDMX4(bh[1], bk + 16*208);
                #pragma unroll
                for (int mt = 0; mt < 2; mt++)
                    #pragma unroll
                    for (int nt = 0; nt < 4; nt++) {
                        const int pr = nt >> 1, sub = (nt & 1)*2;
                        MMA16816(acc[mt][0][nt], ah[mt], bh[pr][sub], bh[pr][sub+1]);
                    }
            }
        }
        __syncthreads();
        if (tid == 0 && c + 2 <= 4) {
            const int nc = c + 2;
            const uint32_t mb = sb + 8*(c & 1);
            if (nc < 4) {
                MBAR_EXPECT(mb, BL);
                bulk_g2s(buf, g_Bh + (size_t)nc*128*JP, BL, mb);
            } else {
                MBAR_EXPECT(mb, TLB);
                bulk_g2s(buf, g_Th, TLB, mb);
            }
        }

        // epilogue stores
        if (c < 4) {
            #pragma unroll
            for (int nh = 0; nh < 2; nh++)
                #pragma unroll
                for (int nt = 0; nt < 4; nt++) {
                    int d = c*128 + wn*64 + nh*32 + nt*8 + qid*2;
                    float bx = __ldg(b_unify + d), by = __ldg(b_unify + d + 1);
                    #pragma unroll
                    for (int mt = 0; mt < 2; mt++) {
                        int row = n0 + wm*32 + mt*16 + grp;
                        float2 o0 = make_float2(acc[mt][nh][nt][0] + bx, acc[mt][nh][nt][1] + by);
                        float2 o1 = make_float2(acc[mt][nh][nt][2] + bx, acc[mt][nh][nt][3] + by);
                        *(float2*)(out_emb + (size_t)row*D + d)     = o0;
                        *(float2*)(out_emb + (size_t)(row+8)*D + d) = o1;
                    }
                }
        } else if (wn == 0) {
            #pragma unroll
            for (int nt = 0; nt < 3; nt++) {     // d <= 22
                int d = nt*8 + qid*2;
                float bx = __ldg(b_time + d), by = __ldg(b_time + d + 1);
                #pragma unroll
                for (int mt = 0; mt < 2; mt++) {
                    int row = n0 + wm*32 + mt*16 + grp;
                    float2 o0 = make_float2(acc[mt][0][nt][0] + bx, acc[mt][0][nt][1] + by);
                    float2 o1 = make_float2(acc[mt][0][nt][2] + bx, acc[mt][0][nt][3] + by);
                    *(float2*)(out_tl + (size_t)row*TS + d)     = o0;
                    *(float2*)(out_tl + (size_t)(row+8)*TS + d) = o1;
                }
            }
        }
    }
}

// ---------------- launch ----------------
extern "C" void kernel_launch(void* const* d_in, const int* in_sizes, int n_in,
                              void* d_out, int out_size)
{
    const float* ts_emb    = (const float*)d_in[0];
    const int*   user_x    = (const int*)  d_in[3];
    const int*   hour_x    = (const int*)  d_in[4];
    const int*   hour_mask = (const int*)  d_in[5];
    const float* upt       = (const float*)d_in[6];
    const float* Wq        = (const float*)d_in[7];
    const float* bq        = (const float*)d_in[8];
    const float* Wk        = (const float*)d_in[9];
    const float* bk        = (const float*)d_in[10];
    const float* Wv        = (const float*)d_in[11];
    const float* bv        = (const float*)d_in[12];
    const float* Wu        = (const float*)d_in[13];
    const float* bu        = (const float*)d_in[14];
    const float* Wt        = (const float*)d_in[15];
    const float* bt        = (const float*)d_in[16];

    float* out_emb = (float*)d_out;
    float* out_tl  = out_emb + (size_t)NPOS * D;

    cudaFuncSetAttribute(k_main, cudaFuncAttributeMaxDynamicSharedMemorySize, FM_TOTAL);

    k_pre1<<<1088, 256>>>(ts_emb, user_x, upt, Wq, bq, Wk, bk, Wv, bv);
    k_pre23<<<936, 256>>>(Wu, Wt);
    k_main<<<256, 256, FM_TOTAL>>>(hour_x, hour_mask, bu, bt, out_emb, out_tl);
}